// round 2
// baseline (speedup 1.0000x reference)
#include <cuda_runtime.h>
#include <cstdint>
#include <cstddef>

#define B_   128
#define P_   625
#define ENC_ 512
#define A_   256
#define E_   256
#define H_   512
#define V_   70
#define T_   70
#define G4_  2048   // 4*H
#define KX_  1280   // E + ENC + H
#define NHP_ 768    // A + H  (att2 | gate-pre)

// ---------------- device scratch (static; no runtime allocation) ----------------
__device__ float g_att1[(size_t)B_ * P_ * A_];   // 81.92 MB
__device__ float g_h[B_ * H_];
__device__ float g_c[B_ * H_];
__device__ float g_xcat[B_ * KX_];               // [emb(256) | awe_gated(512) | h(512)]
__device__ float g_hproj[2 * B_ * NHP_];         // K-split partials of h @ [Wd|Wb]
__device__ float g_gates[2 * B_ * G4_];          // K-split partials of xcat @ Wcat
__device__ float g_preds[B_ * V_];
__device__ float g_Wcat[(size_t)KX_ * G4_];      // [Wih ; Whh]  10.49 MB
__device__ float g_Whb[H_ * NHP_];               // columns [Wd | Wb]
__device__ float g_WfcT[V_ * H_];                // Wfc transposed
__device__ int   g_done;

// ---------------- helpers ----------------
__device__ __forceinline__ float warp_sum(float v) {
#pragma unroll
  for (int o = 16; o; o >>= 1) v += __shfl_down_sync(0xffffffffu, v, o);
  return v;
}
__device__ __forceinline__ float warp_max(float v) {
#pragma unroll
  for (int o = 16; o; o >>= 1) v = fmaxf(v, __shfl_down_sync(0xffffffffu, v, o));
  return v;
}
__device__ __forceinline__ float sigf(float x) { return 1.f / (1.f + expf(-x)); }

// ---------------- generic tiled fp32 GEMM: C[z] = A[:,k-slice] @ B[k-slice,:] ----------------
// 64x64 tile, K-chunk 16, 256 threads, 4x4 per thread. M,N divisible by 64; K/gridDim.z divisible by 16.
__global__ void __launch_bounds__(256) gemm64(
    const float* __restrict__ A, const float* __restrict__ B,
    float* __restrict__ C, const float* __restrict__ bias,
    int M, int N, int K) {
  const int tid   = threadIdx.x;
  const int mBase = blockIdx.y * 64;
  const int nBase = blockIdx.x * 64;
  const int kPer  = K / gridDim.z;
  const int k0    = blockIdx.z * kPer;

  __shared__ float As[16][68];
  __shared__ float Bs[16][68];

  const int tm = (tid >> 4) << 2;
  const int tn = (tid & 15) << 2;
  const int lm = tid >> 2;           // A row within tile
  const int lk = (tid & 3) << 2;     // A k offset (0,4,8,12)
  const int bk = tid >> 4;           // B k row (0..15)
  const int bn = (tid & 15) << 2;    // B n offset

  float acc[4][4] = {};

  for (int kk = 0; kk < kPer; kk += 16) {
    const float4 av = *reinterpret_cast<const float4*>(
        A + (size_t)(mBase + lm) * K + (k0 + kk + lk));
    const float4 bv = *reinterpret_cast<const float4*>(
        B + (size_t)(k0 + kk + bk) * N + (nBase + bn));
    __syncthreads();
    As[lk + 0][lm] = av.x; As[lk + 1][lm] = av.y;
    As[lk + 2][lm] = av.z; As[lk + 3][lm] = av.w;
    Bs[bk][bn + 0] = bv.x; Bs[bk][bn + 1] = bv.y;
    Bs[bk][bn + 2] = bv.z; Bs[bk][bn + 3] = bv.w;
    __syncthreads();
#pragma unroll
    for (int k = 0; k < 16; k++) {
      float a0 = As[k][tm + 0], a1 = As[k][tm + 1], a2 = As[k][tm + 2], a3 = As[k][tm + 3];
      float b0 = Bs[k][tn + 0], b1 = Bs[k][tn + 1], b2 = Bs[k][tn + 2], b3 = Bs[k][tn + 3];
      acc[0][0] = fmaf(a0, b0, acc[0][0]); acc[0][1] = fmaf(a0, b1, acc[0][1]);
      acc[0][2] = fmaf(a0, b2, acc[0][2]); acc[0][3] = fmaf(a0, b3, acc[0][3]);
      acc[1][0] = fmaf(a1, b0, acc[1][0]); acc[1][1] = fmaf(a1, b1, acc[1][1]);
      acc[1][2] = fmaf(a1, b2, acc[1][2]); acc[1][3] = fmaf(a1, b3, acc[1][3]);
      acc[2][0] = fmaf(a2, b0, acc[2][0]); acc[2][1] = fmaf(a2, b1, acc[2][1]);
      acc[2][2] = fmaf(a2, b2, acc[2][2]); acc[2][3] = fmaf(a2, b3, acc[2][3]);
      acc[3][0] = fmaf(a3, b0, acc[3][0]); acc[3][1] = fmaf(a3, b1, acc[3][1]);
      acc[3][2] = fmaf(a3, b2, acc[3][2]); acc[3][3] = fmaf(a3, b3, acc[3][3]);
    }
  }

  float* Cz = C + (size_t)blockIdx.z * M * N;
#pragma unroll
  for (int i = 0; i < 4; i++) {
#pragma unroll
    for (int jj = 0; jj < 4; jj++) {
      const int n = nBase + tn + jj;
      float v = acc[i][jj];
      if (bias) v += bias[n];
      Cz[(size_t)(mBase + tm + i) * N + n] = v;
    }
  }
}

// ---------------- one-time prep kernels ----------------
__global__ void prep_weights(const float* __restrict__ Wd, const float* __restrict__ Wb,
                             const float* __restrict__ Wfc) {
  const int idx = blockIdx.x * 256 + threadIdx.x;
  if (idx < H_ * NHP_) {
    const int k = idx / NHP_, n = idx % NHP_;
    g_Whb[idx] = (n < A_) ? Wd[k * A_ + n] : Wb[k * H_ + (n - A_)];
  }
  if (idx < V_ * H_) {
    const int v = idx / H_, k = idx % H_;
    g_WfcT[idx] = Wfc[k * V_ + v];
  }
}

__global__ void init_kernel(const float* __restrict__ emb) {
  const int b = blockIdx.x, i = threadIdx.x;  // 256
  g_xcat[b * KX_ + i] = emb[68 * E_ + i];     // START_TOK = 68
  if (b == 0 && i == 0) g_done = 0;
}

__global__ void mean_init_kernel(const float* __restrict__ enc,
                                 const float* __restrict__ Wh0, const float* __restrict__ bh0,
                                 const float* __restrict__ Wc0, const float* __restrict__ bc0) {
  const int b = blockIdx.x, e = threadIdx.x;  // 512
  const float* p = enc + (size_t)b * P_ * ENC_ + e;
  float s = 0.f;
#pragma unroll 5
  for (int i = 0; i < P_; i++) s += p[(size_t)i * ENC_];
  __shared__ float ms[ENC_];
  ms[e] = s / 625.f;
  __syncthreads();
  float h = bh0[e], c = bc0[e];
#pragma unroll 4
  for (int k = 0; k < ENC_; k++) {
    const float m = ms[k];
    h = fmaf(m, Wh0[k * H_ + e], h);
    c = fmaf(m, Wc0[k * H_ + e], c);
  }
  g_h[b * H_ + e] = h;
  g_c[b * H_ + e] = c;
  g_xcat[b * KX_ + E_ + H_ + e] = h;
}

// ---------------- per-step: fused attention (energy + softmax + gated weighted sum) ----------------
__global__ void __launch_bounds__(1024) att_kernel(
    const float* __restrict__ enc, const float* __restrict__ wf,
    const float* __restrict__ bfp, const float* __restrict__ bd,
    const float* __restrict__ bb) {
  const int b = blockIdx.x;
  const int t = threadIdx.x;
  __shared__ float att2_s[A_];
  __shared__ float wf_s[A_];
  __shared__ float hg_s[H_];
  __shared__ float e_s[P_];
  __shared__ float red_s[32];
  __shared__ float part_s[1024];
  __shared__ float s_bf, s_max, s_inv;

  if (t == 0) s_bf = bfp[0];
  if (t < A_) {
    att2_s[t] = g_hproj[b * NHP_ + t] + g_hproj[B_ * NHP_ + b * NHP_ + t] + bd[t];
    wf_s[t] = wf[t];
  } else if (t >= 256 && t < 768) {
    const int j = t - 256;
    const float x = g_hproj[b * NHP_ + A_ + j] + g_hproj[B_ * NHP_ + b * NHP_ + A_ + j] + bb[j];
    hg_s[j] = sigf(x);
  }
  __syncthreads();

  const int wid = t >> 5, lane = t & 31;

  // energies: e[p] = sum_a relu(att1 + att2)*wf + bf     (reads att1: 640KB/block)
  const float* a1b = g_att1 + (size_t)b * (P_ * A_);
  for (int p = wid; p < P_; p += 32) {
    const float* ap = a1b + p * A_;
    float s = 0.f;
#pragma unroll
    for (int i = 0; i < 8; i++) {
      const int a = i * 32 + lane;
      const float x = ap[a] + att2_s[a];
      s = fmaf(fmaxf(x, 0.f), wf_s[a], s);
    }
    s = warp_sum(s);
    if (lane == 0) e_s[p] = s + s_bf;
  }
  __syncthreads();

  // softmax (store exp in e_s, keep 1/sum)
  float lm = -3.402823466e38f;
  if (t < P_) lm = e_s[t];
  lm = warp_max(lm);
  if (lane == 0) red_s[wid] = lm;
  __syncthreads();
  if (wid == 0) {
    float m = warp_max(red_s[lane]);
    if (lane == 0) s_max = m;
  }
  __syncthreads();
  float ls = 0.f;
  if (t < P_) {
    const float ex = expf(e_s[t] - s_max);
    e_s[t] = ex;
    ls = ex;
  }
  ls = warp_sum(ls);
  if (lane == 0) red_s[wid] = ls;
  __syncthreads();
  if (wid == 0) {
    float sm = warp_sum(red_s[lane]);
    if (lane == 0) s_inv = 1.f / sm;
  }
  __syncthreads();

  // gated attention-weighted encoding (reads enc: 1.28MB/block)
  const float* encb = enc + (size_t)b * (P_ * ENC_);
  const int j = t & (H_ - 1);
  const int ph = t >> 9;  // 0/1: interleaved p
  float acc = 0.f;
  int p = ph;
  for (; p + 14 < P_; p += 16) {
    float v[8];
#pragma unroll
    for (int u = 0; u < 8; u++) v[u] = encb[(size_t)(p + 2 * u) * ENC_ + j];
#pragma unroll
    for (int u = 0; u < 8; u++) acc = fmaf(e_s[p + 2 * u], v[u], acc);
  }
  for (; p < P_; p += 2) acc = fmaf(e_s[p], encb[(size_t)p * ENC_ + j], acc);
  part_s[t] = acc;
  __syncthreads();
  if (t < H_) {
    const float awe = (part_s[t] + part_s[t + 512]) * s_inv;
    g_xcat[b * KX_ + E_ + t] = hg_s[t] * awe;
  }
}

// ---------------- per-step: LSTM elementwise + preds ----------------
__global__ void __launch_bounds__(512) lstm_kernel(
    const float* __restrict__ bih, const float* __restrict__ bhh,
    const float* __restrict__ bfc) {
  const int b = blockIdx.x, j = threadIdx.x;  // 512
  const float* q0 = g_gates + (size_t)b * G4_;
  const float* q1 = g_gates + (size_t)(B_ + b) * G4_;
  const float gi = q0[j] + q1[j] + bih[j] + bhh[j];
  const float gf = q0[j + 512]  + q1[j + 512]  + bih[j + 512]  + bhh[j + 512];
  const float gg = q0[j + 1024] + q1[j + 1024] + bih[j + 1024] + bhh[j + 1024];
  const float go = q0[j + 1536] + q1[j + 1536] + bih[j + 1536] + bhh[j + 1536];
  const float c  = g_c[b * H_ + j];
  const float cn = sigf(gf) * c + sigf(gi) * tanhf(gg);
  const float hn = sigf(go) * tanhf(cn);
  g_c[b * H_ + j] = cn;
  g_h[b * H_ + j] = hn;
  g_xcat[b * KX_ + E_ + H_ + j] = hn;

  __shared__ float hs[H_];
  hs[j] = hn;
  __syncthreads();
  const int wid = j >> 5, lane = j & 31;
  for (int v = wid; v < V_; v += 16) {
    const float* w = g_WfcT + v * H_;
    float s = 0.f;
#pragma unroll 4
    for (int k = lane; k < H_; k += 32) s = fmaf(hs[k], w[k], s);
    s = warp_sum(s);
    if (lane == 0) g_preds[b * V_ + v] = s + bfc[v];
  }
}

// ---------------- per-step: argmax, done flag, emb feedback, output write ----------------
__global__ void __launch_bounds__(1024) finish_kernel(
    const float* __restrict__ emb, float* __restrict__ out, int step) {
  const int t = threadIdx.x;
  __shared__ float rmax[B_];
  __shared__ int ridx[B_];
  __shared__ int s_done_prev;
  if (t == 0) s_done_prev = g_done;
  if (t < B_) {
    const float* pr = g_preds + t * V_;
    float m = pr[0];
    int mi = 0;
#pragma unroll
    for (int v = 1; v < V_; v++) {
      const float x = pr[v];
      if (x > m) { m = x; mi = v; }
    }
    rmax[t] = m;
    ridx[t] = mi;
  }
  __syncthreads();
  if (t == 0) {
    float bm = rmax[0];
    int bb2 = 0;
    for (int i = 1; i < B_; i++)
      if (rmax[i] > bm) { bm = rmax[i]; bb2 = i; }
    const int flat = bb2 * V_ + ridx[bb2];
    g_done = s_done_prev | (flat == 69);  // END_TOK
  }
  __syncthreads();
  const int dprev = s_done_prev;
  for (int idx = t; idx < B_ * V_; idx += 1024) {
    const int b = idx / V_, v = idx % V_;
    out[(size_t)b * (T_ * V_) + (size_t)step * V_ + v] = dprev ? 0.f : g_preds[idx];
  }
  for (int idx = t; idx < B_ * E_; idx += 1024) {
    const int b = idx >> 8, i = idx & 255;
    g_xcat[b * KX_ + i] = emb[ridx[b] * E_ + i];
  }
}

// ---------------- launch ----------------
extern "C" void kernel_launch(void* const* d_in, const int* in_sizes, int n_in,
                              void* d_out, int out_size) {
  const float* enc = (const float*)d_in[0];
  const float* emb = (const float*)d_in[1];
  const float* We  = (const float*)d_in[2];
  const float* be  = (const float*)d_in[3];
  const float* Wd  = (const float*)d_in[4];
  const float* bd  = (const float*)d_in[5];
  const float* wf  = (const float*)d_in[6];
  const float* bf  = (const float*)d_in[7];
  const float* Wh0 = (const float*)d_in[8];
  const float* bh0 = (const float*)d_in[9];
  const float* Wc0 = (const float*)d_in[10];
  const float* bc0 = (const float*)d_in[11];
  const float* Wb  = (const float*)d_in[12];
  const float* bb  = (const float*)d_in[13];
  const float* Wih = (const float*)d_in[14];
  const float* Whh = (const float*)d_in[15];
  const float* bih = (const float*)d_in[16];
  const float* bhh = (const float*)d_in[17];
  const float* Wfc = (const float*)d_in[18];
  const float* bfc = (const float*)d_in[19];
  float* out = (float*)d_out;

  float *p_att1, *p_h, *p_xcat, *p_hproj, *p_gates, *p_Wcat, *p_Whb;
  cudaGetSymbolAddress((void**)&p_att1,  g_att1);
  cudaGetSymbolAddress((void**)&p_h,     g_h);
  cudaGetSymbolAddress((void**)&p_xcat,  g_xcat);
  cudaGetSymbolAddress((void**)&p_hproj, g_hproj);
  cudaGetSymbolAddress((void**)&p_gates, g_gates);
  cudaGetSymbolAddress((void**)&p_Wcat,  g_Wcat);
  cudaGetSymbolAddress((void**)&p_Whb,   g_Whb);

  // concat [Wih ; Whh] -> Wcat (async D2D copies; capture-legal)
  cudaMemcpyAsync(p_Wcat, Wih, sizeof(float) * (size_t)768 * G4_,
                  cudaMemcpyDeviceToDevice, 0);
  cudaMemcpyAsync(p_Wcat + (size_t)768 * G4_, Whh, sizeof(float) * (size_t)512 * G4_,
                  cudaMemcpyDeviceToDevice, 0);

  prep_weights<<<1536, 256>>>(Wd, Wb, Wfc);
  init_kernel<<<B_, 256>>>(emb);
  mean_init_kernel<<<B_, 512>>>(enc, Wh0, bh0, Wc0, bc0);

  // att1 = enc @ We + be  : M=80000, N=256, K=512
  gemm64<<<dim3(256 / 64, (B_ * P_) / 64, 1), 256>>>(enc, We, p_att1, be,
                                                     B_ * P_, 256, 512);

  for (int step = 0; step < T_; step++) {
    // hproj = h @ [Wd|Wb]  : M=128, N=768, K=512, Ksplit=2
    gemm64<<<dim3(NHP_ / 64, B_ / 64, 2), 256>>>(p_h, p_Whb, p_hproj, nullptr,
                                                 B_, NHP_, 512);
    att_kernel<<<B_, 1024>>>(enc, wf, bf, bd, bb);
    // gates = xcat @ Wcat : M=128, N=2048, K=1280, Ksplit=2
    gemm64<<<dim3(G4_ / 64, B_ / 64, 2), 256>>>(p_xcat, p_Wcat, p_gates, nullptr,
                                                B_, G4_, KX_);
    lstm_kernel<<<B_, 512>>>(bih, bhh, bfc);
    finish_kernel<<<1, 1024>>>(emb, out, step);
  }
}

// round 8
// speedup vs baseline: 1.4214x; 1.4214x over previous
#include <cuda_runtime.h>
#include <cstdint>
#include <cstddef>

#define B_   128
#define P_   625
#define ENC_ 512
#define A_   256
#define E_   256
#define H_   512
#define V_   70
#define T_   70
#define G4_  2048   // 4*H
#define KX_  1280   // E + ENC + H
#define NHP_ 768    // A + H  (att2 | gate-pre)
#define NZH_ 4      // K-split for hproj
#define NZG_ 4      // K-split for gates

// ---------------- device scratch (static; no runtime allocation) ----------------
__device__ float g_att1[(size_t)B_ * P_ * A_];   // 81.92 MB (fp32 — precision is load-bearing)
__device__ float g_h[B_ * H_];
__device__ float g_c[B_ * H_];
__device__ float g_xcat[B_ * KX_];               // [emb(256) | awe_gated(512) | h(512)]
__device__ float g_hproj[NZH_ * B_ * NHP_];      // K-split partials of h @ [Wd|Wb]
__device__ float g_gates[NZG_ * B_ * G4_];       // K-split partials of xcat @ Wcat
__device__ float g_preds[B_ * V_];
__device__ float g_Wcat[(size_t)KX_ * G4_];      // [Wih ; Whh]  10.49 MB
__device__ float g_Whb[H_ * NHP_];               // columns [Wd | Wb]
__device__ float g_WfcT[V_ * H_];                // Wfc transposed
__device__ int   g_done;

// ---------------- helpers ----------------
__device__ __forceinline__ float warp_sum(float v) {
#pragma unroll
  for (int o = 16; o; o >>= 1) v += __shfl_down_sync(0xffffffffu, v, o);
  return v;
}
__device__ __forceinline__ float warp_max(float v) {
#pragma unroll
  for (int o = 16; o; o >>= 1) v = fmaxf(v, __shfl_down_sync(0xffffffffu, v, o));
  return v;
}
__device__ __forceinline__ float sigf(float x) { return 1.f / (1.f + expf(-x)); }

// ---------------- generic tiled fp32 GEMM: C[z] = A[:,k-slice] @ B[k-slice,:] ----------------
// 64x64 tile, K-chunk 16, 256 threads, 4x4 per thread. M,N div by 64; K/gridDim.z div by 16.
__global__ void __launch_bounds__(256) gemm64(
    const float* __restrict__ A, const float* __restrict__ B,
    float* __restrict__ C, const float* __restrict__ bias,
    int M, int N, int K) {
  const int tid   = threadIdx.x;
  const int mBase = blockIdx.y * 64;
  const int nBase = blockIdx.x * 64;
  const int kPer  = K / gridDim.z;
  const int k0    = blockIdx.z * kPer;

  __shared__ float As[16][68];
  __shared__ float Bs[16][68];

  const int tm = (tid >> 4) << 2;
  const int tn = (tid & 15) << 2;
  const int lm = tid >> 2;           // A row within tile
  const int lk = (tid & 3) << 2;     // A k offset (0,4,8,12)
  const int bk = tid >> 4;           // B k row (0..15)
  const int bn = (tid & 15) << 2;    // B n offset

  float acc[4][4] = {};

  for (int kk = 0; kk < kPer; kk += 16) {
    const float4 av = *reinterpret_cast<const float4*>(
        A + (size_t)(mBase + lm) * K + (k0 + kk + lk));
    const float4 bv = *reinterpret_cast<const float4*>(
        B + (size_t)(k0 + kk + bk) * N + (nBase + bn));
    __syncthreads();
    As[lk + 0][lm] = av.x; As[lk + 1][lm] = av.y;
    As[lk + 2][lm] = av.z; As[lk + 3][lm] = av.w;
    Bs[bk][bn + 0] = bv.x; Bs[bk][bn + 1] = bv.y;
    Bs[bk][bn + 2] = bv.z; Bs[bk][bn + 3] = bv.w;
    __syncthreads();
#pragma unroll
    for (int k = 0; k < 16; k++) {
      float a0 = As[k][tm + 0], a1 = As[k][tm + 1], a2 = As[k][tm + 2], a3 = As[k][tm + 3];
      float b0 = Bs[k][tn + 0], b1 = Bs[k][tn + 1], b2 = Bs[k][tn + 2], b3 = Bs[k][tn + 3];
      acc[0][0] = fmaf(a0, b0, acc[0][0]); acc[0][1] = fmaf(a0, b1, acc[0][1]);
      acc[0][2] = fmaf(a0, b2, acc[0][2]); acc[0][3] = fmaf(a0, b3, acc[0][3]);
      acc[1][0] = fmaf(a1, b0, acc[1][0]); acc[1][1] = fmaf(a1, b1, acc[1][1]);
      acc[1][2] = fmaf(a1, b2, acc[1][2]); acc[1][3] = fmaf(a1, b3, acc[1][3]);
      acc[2][0] = fmaf(a2, b0, acc[2][0]); acc[2][1] = fmaf(a2, b1, acc[2][1]);
      acc[2][2] = fmaf(a2, b2, acc[2][2]); acc[2][3] = fmaf(a2, b3, acc[2][3]);
      acc[3][0] = fmaf(a3, b0, acc[3][0]); acc[3][1] = fmaf(a3, b1, acc[3][1]);
      acc[3][2] = fmaf(a3, b2, acc[3][2]); acc[3][3] = fmaf(a3, b3, acc[3][3]);
    }
  }

  float* Cz = C + (size_t)blockIdx.z * M * N;
#pragma unroll
  for (int i = 0; i < 4; i++) {
#pragma unroll
    for (int jj = 0; jj < 4; jj++) {
      const int n = nBase + tn + jj;
      float v = acc[i][jj];
      if (bias) v += bias[n];
      Cz[(size_t)(mBase + tm + i) * N + n] = v;
    }
  }
}

// ---------------- one-time prep kernels ----------------
__global__ void prep_weights(const float* __restrict__ Wd, const float* __restrict__ Wb,
                             const float* __restrict__ Wfc) {
  const int idx = blockIdx.x * 256 + threadIdx.x;
  if (idx < H_ * NHP_) {
    const int k = idx / NHP_, n = idx % NHP_;
    g_Whb[idx] = (n < A_) ? Wd[k * A_ + n] : Wb[k * H_ + (n - A_)];
  }
  if (idx < V_ * H_) {
    const int v = idx / H_, k = idx % H_;
    g_WfcT[idx] = Wfc[k * V_ + v];
  }
}

__global__ void init_kernel(const float* __restrict__ emb) {
  const int b = blockIdx.x, i = threadIdx.x;  // 256
  g_xcat[b * KX_ + i] = emb[68 * E_ + i];     // START_TOK = 68
  if (b == 0 && i == 0) g_done = 0;
}

__global__ void mean_init_kernel(const float* __restrict__ enc,
                                 const float* __restrict__ Wh0, const float* __restrict__ bh0,
                                 const float* __restrict__ Wc0, const float* __restrict__ bc0) {
  const int b = blockIdx.x, e = threadIdx.x;  // 512
  const float* p = enc + (size_t)b * P_ * ENC_ + e;
  float s = 0.f;
#pragma unroll 5
  for (int i = 0; i < P_; i++) s += p[(size_t)i * ENC_];
  __shared__ float ms[ENC_];
  ms[e] = s / 625.f;
  __syncthreads();
  float h = bh0[e], c = bc0[e];
#pragma unroll 4
  for (int k = 0; k < ENC_; k++) {
    const float m = ms[k];
    h = fmaf(m, Wh0[k * H_ + e], h);
    c = fmaf(m, Wc0[k * H_ + e], c);
  }
  g_h[b * H_ + e] = h;
  g_c[b * H_ + e] = c;
  g_xcat[b * KX_ + E_ + H_ + e] = h;
}

// ---------------- finish body (argmax/done/out/emb) — runs as extra block in att ----------------
__device__ __forceinline__ void finish_body(const float* __restrict__ emb,
                                            float* __restrict__ out, int fstep) {
  const int t = threadIdx.x;
  __shared__ float rmax[B_];
  __shared__ int ridx[B_];
  __shared__ int s_done_prev;
  if (t == 0) s_done_prev = g_done;
  if (t < B_) {
    const float* pr = g_preds + t * V_;
    float m = pr[0];
    int mi = 0;
#pragma unroll
    for (int v = 1; v < V_; v++) {
      const float x = pr[v];
      if (x > m) { m = x; mi = v; }
    }
    rmax[t] = m;
    ridx[t] = mi;
  }
  __syncthreads();
  if (t == 0) {
    float bm = rmax[0];
    int bb2 = 0;
    for (int i = 1; i < B_; i++)
      if (rmax[i] > bm) { bm = rmax[i]; bb2 = i; }
    const int flat = bb2 * V_ + ridx[bb2];
    g_done = s_done_prev | (flat == 69);  // END_TOK
  }
  __syncthreads();
  const int dprev = s_done_prev;
  for (int idx = t; idx < B_ * V_; idx += 1024) {
    const int b = idx / V_, v = idx % V_;
    out[(size_t)b * (T_ * V_) + (size_t)fstep * V_ + v] = dprev ? 0.f : g_preds[idx];
  }
  for (int idx = t; idx < B_ * E_; idx += 1024) {
    const int b = idx >> 8, i = idx & 255;
    g_xcat[b * KX_ + i] = emb[ridx[b] * E_ + i];
  }
}

// ---------------- per-step: fused attention + (finish of previous step in block B_) ----------
__global__ void __launch_bounds__(1024) att_kernel(
    const float* __restrict__ enc, const float* __restrict__ wf,
    const float* __restrict__ bfp, const float* __restrict__ bd,
    const float* __restrict__ bb, const float* __restrict__ emb,
    float* __restrict__ out, int step) {
  if (blockIdx.x == B_) {               // finish work for step-1 (independent of att inputs)
    if (step > 0) finish_body(emb, out, step - 1);
    return;
  }
  const int b = blockIdx.x;
  const int t = threadIdx.x;
  __shared__ float att2_s[A_];
  __shared__ float wf_s[A_];
  __shared__ float hg_s[H_];
  __shared__ float e_s[P_];
  __shared__ float red_s[32];
  __shared__ float part_s[1024];
  __shared__ float s_bf, s_max, s_inv;

  if (t == 0) s_bf = bfp[0];
  if (t < A_) {
    float v = bd[t];
#pragma unroll
    for (int z = 0; z < NZH_; z++) v += g_hproj[z * B_ * NHP_ + b * NHP_ + t];
    att2_s[t] = v;
    wf_s[t] = wf[t];
  } else if (t >= 256 && t < 768) {
    const int j = t - 256;
    float x = bb[j];
#pragma unroll
    for (int z = 0; z < NZH_; z++) x += g_hproj[z * B_ * NHP_ + b * NHP_ + A_ + j];
    hg_s[j] = sigf(x);
  }
  __syncthreads();

  const int wid = t >> 5, lane = t & 31;

  // energies: e[p] = sum_a relu(att1 + att2)*wf + bf   (reads fp32 att1: 640KB/block, float4)
  const float* a1b = g_att1 + (size_t)b * (P_ * A_);
  for (int p = wid; p < P_; p += 32) {
    const float4* ap = reinterpret_cast<const float4*>(a1b + (size_t)p * A_);
    const float4 v0 = ap[lane];
    const float4 v1 = ap[lane + 32];
    float s = 0.f;
    const int a0 = lane * 4;
    const int a1 = 128 + lane * 4;
    s = fmaf(fmaxf(v0.x + att2_s[a0 + 0], 0.f), wf_s[a0 + 0], s);
    s = fmaf(fmaxf(v0.y + att2_s[a0 + 1], 0.f), wf_s[a0 + 1], s);
    s = fmaf(fmaxf(v0.z + att2_s[a0 + 2], 0.f), wf_s[a0 + 2], s);
    s = fmaf(fmaxf(v0.w + att2_s[a0 + 3], 0.f), wf_s[a0 + 3], s);
    s = fmaf(fmaxf(v1.x + att2_s[a1 + 0], 0.f), wf_s[a1 + 0], s);
    s = fmaf(fmaxf(v1.y + att2_s[a1 + 1], 0.f), wf_s[a1 + 1], s);
    s = fmaf(fmaxf(v1.z + att2_s[a1 + 2], 0.f), wf_s[a1 + 2], s);
    s = fmaf(fmaxf(v1.w + att2_s[a1 + 3], 0.f), wf_s[a1 + 3], s);
    s = warp_sum(s);
    if (lane == 0) e_s[p] = s + s_bf;
  }
  __syncthreads();

  // softmax (store exp in e_s, keep 1/sum)
  float lm = -3.402823466e38f;
  if (t < P_) lm = e_s[t];
  lm = warp_max(lm);
  if (lane == 0) red_s[wid] = lm;
  __syncthreads();
  if (wid == 0) {
    float m = warp_max(red_s[lane]);
    if (lane == 0) s_max = m;
  }
  __syncthreads();
  float ls = 0.f;
  if (t < P_) {
    const float ex = expf(e_s[t] - s_max);
    e_s[t] = ex;
    ls = ex;
  }
  ls = warp_sum(ls);
  if (lane == 0) red_s[wid] = ls;
  __syncthreads();
  if (wid == 0) {
    float sm = warp_sum(red_s[lane]);
    if (lane == 0) s_inv = 1.f / sm;
  }
  __syncthreads();

  // gated attention-weighted encoding (reads enc: 1.28MB/block)
  const float* encb = enc + (size_t)b * (P_ * ENC_);
  const int j = t & (H_ - 1);
  const int ph = t >> 9;  // 0/1: interleaved p
  float acc = 0.f;
  int p = ph;
  for (; p + 14 < P_; p += 16) {
    float v[8];
#pragma unroll
    for (int u = 0; u < 8; u++) v[u] = encb[(size_t)(p + 2 * u) * ENC_ + j];
#pragma unroll
    for (int u = 0; u < 8; u++) acc = fmaf(e_s[p + 2 * u], v[u], acc);
  }
  for (; p < P_; p += 2) acc = fmaf(e_s[p], encb[(size_t)p * ENC_ + j], acc);
  part_s[t] = acc;
  __syncthreads();
  if (t < H_) {
    const float awe = (part_s[t] + part_s[t + 512]) * s_inv;
    g_xcat[b * KX_ + E_ + t] = hg_s[t] * awe;
  }
}

// ---------------- per-step: LSTM elementwise + preds ----------------
__global__ void __launch_bounds__(512) lstm_kernel(
    const float* __restrict__ bih, const float* __restrict__ bhh,
    const float* __restrict__ bfc) {
  const int b = blockIdx.x, j = threadIdx.x;  // 512
  float gi = bih[j] + bhh[j];
  float gf = bih[j + 512] + bhh[j + 512];
  float gg = bih[j + 1024] + bhh[j + 1024];
  float go = bih[j + 1536] + bhh[j + 1536];
#pragma unroll
  for (int z = 0; z < NZG_; z++) {
    const float* q = g_gates + (size_t)(z * B_ + b) * G4_;
    gi += q[j];
    gf += q[j + 512];
    gg += q[j + 1024];
    go += q[j + 1536];
  }
  const float c  = g_c[b * H_ + j];
  const float cn = sigf(gf) * c + sigf(gi) * tanhf(gg);
  const float hn = sigf(go) * tanhf(cn);
  g_c[b * H_ + j] = cn;
  g_h[b * H_ + j] = hn;
  g_xcat[b * KX_ + E_ + H_ + j] = hn;

  __shared__ float hs[H_];
  hs[j] = hn;
  __syncthreads();
  const int wid = j >> 5, lane = j & 31;
  for (int v = wid; v < V_; v += 16) {
    const float* w = g_WfcT + v * H_;
    float s = 0.f;
#pragma unroll 4
    for (int k = lane; k < H_; k += 32) s = fmaf(hs[k], w[k], s);
    s = warp_sum(s);
    if (lane == 0) g_preds[b * V_ + v] = s + bfc[v];
  }
}

// ---------------- final finish (last step) ----------------
__global__ void __launch_bounds__(1024) finish_kernel(
    const float* __restrict__ emb, float* __restrict__ out, int fstep) {
  finish_body(emb, out, fstep);
}

// ---------------- launch ----------------
extern "C" void kernel_launch(void* const* d_in, const int* in_sizes, int n_in,
                              void* d_out, int out_size) {
  const float* enc = (const float*)d_in[0];
  const float* emb = (const float*)d_in[1];
  const float* We  = (const float*)d_in[2];
  const float* be  = (const float*)d_in[3];
  const float* Wd  = (const float*)d_in[4];
  const float* bd  = (const float*)d_in[5];
  const float* wf  = (const float*)d_in[6];
  const float* bf  = (const float*)d_in[7];
  const float* Wh0 = (const float*)d_in[8];
  const float* bh0 = (const float*)d_in[9];
  const float* Wc0 = (const float*)d_in[10];
  const float* bc0 = (const float*)d_in[11];
  const float* Wb  = (const float*)d_in[12];
  const float* bb  = (const float*)d_in[13];
  const float* Wih = (const float*)d_in[14];
  const float* Whh = (const float*)d_in[15];
  const float* bih = (const float*)d_in[16];
  const float* bhh = (const float*)d_in[17];
  const float* Wfc = (const float*)d_in[18];
  const float* bfc = (const float*)d_in[19];
  float* out = (float*)d_out;

  float *p_att1, *p_h, *p_xcat, *p_hproj, *p_gates, *p_Wcat, *p_Whb;
  cudaGetSymbolAddress((void**)&p_att1,  g_att1);
  cudaGetSymbolAddress((void**)&p_h,     g_h);
  cudaGetSymbolAddress((void**)&p_xcat,  g_xcat);
  cudaGetSymbolAddress((void**)&p_hproj, g_hproj);
  cudaGetSymbolAddress((void**)&p_gates, g_gates);
  cudaGetSymbolAddress((void**)&p_Wcat,  g_Wcat);
  cudaGetSymbolAddress((void**)&p_Whb,   g_Whb);

  // concat [Wih ; Whh] -> Wcat (async D2D copies; capture-legal)
  cudaMemcpyAsync(p_Wcat, Wih, sizeof(float) * (size_t)768 * G4_,
                  cudaMemcpyDeviceToDevice, 0);
  cudaMemcpyAsync(p_Wcat + (size_t)768 * G4_, Whh, sizeof(float) * (size_t)512 * G4_,
                  cudaMemcpyDeviceToDevice, 0);

  prep_weights<<<1536, 256>>>(Wd, Wb, Wfc);
  init_kernel<<<B_, 256>>>(emb);
  mean_init_kernel<<<B_, 512>>>(enc, Wh0, bh0, Wc0, bc0);

  // att1 = enc @ We + be : M=80000, N=256, K=512 (fp32)
  gemm64<<<dim3(256 / 64, (B_ * P_) / 64, 1), 256>>>(enc, We, p_att1, be,
                                                     B_ * P_, 256, 512);

  for (int step = 0; step < T_; step++) {
    // hproj = h @ [Wd|Wb]  : M=128, N=768, K=512, Ksplit=4
    gemm64<<<dim3(NHP_ / 64, B_ / 64, NZH_), 256>>>(p_h, p_Whb, p_hproj, nullptr,
                                                    B_, NHP_, 512);
    // att (+ finish of step-1 in block 128)
    att_kernel<<<B_ + 1, 1024>>>(enc, wf, bf, bd, bb, emb, out, step);
    // gates = xcat @ Wcat : M=128, N=2048, K=1280, Ksplit=4
    gemm64<<<dim3(G4_ / 64, B_ / 64, NZG_), 256>>>(p_xcat, p_Wcat, p_gates, nullptr,
                                                   B_, G4_, KX_);
    lstm_kernel<<<B_, 512>>>(bih, bhh, bfc);
  }
  finish_kernel<<<1, 1024>>>(emb, out, T_ - 1);
}

// round 9
// speedup vs baseline: 1.4833x; 1.0435x over previous
#include <cuda_runtime.h>
#include <cstdint>
#include <cstddef>

#define B_   128
#define P_   625
#define ENC_ 512
#define A_   256
#define E_   256
#define H_   512
#define V_   70
#define T_   70
#define G4_  2048   // 4*H
#define KX_  1280   // E + ENC + H
#define NHP_ 768    // A + H  (att2 | gate-pre)
#define NZH_ 8      // K-split for hproj
#define NZG_ 8      // K-split for gates
#define PSPLIT0 313 // energy p-range split

// ---------------- device scratch (static; no runtime allocation) ----------------
__device__ float g_att1[(size_t)B_ * P_ * A_];   // 81.92 MB (fp32 — precision is load-bearing)
__device__ float g_e[B_ * P_];                   // raw energies per step
__device__ float g_h[B_ * H_];
__device__ float g_c[B_ * H_];
__device__ float g_xcat[B_ * KX_];               // [emb(256) | awe_gated(512) | h(512)]
__device__ float g_hproj[NZH_ * B_ * NHP_];      // K-split partials of h @ [Wd|Wb]
__device__ float g_gates[NZG_ * B_ * G4_];       // K-split partials of xcat @ Wcat
__device__ float g_preds[B_ * V_];
__device__ float g_Wcat[(size_t)KX_ * G4_];      // [Wih ; Whh]  10.49 MB
__device__ float g_Whb[H_ * NHP_];               // columns [Wd | Wb]
__device__ float g_WfcT[V_ * H_];                // Wfc transposed
__device__ int   g_done;

// ---------------- helpers ----------------
__device__ __forceinline__ float warp_sum(float v) {
#pragma unroll
  for (int o = 16; o; o >>= 1) v += __shfl_down_sync(0xffffffffu, v, o);
  return v;
}
__device__ __forceinline__ float warp_max(float v) {
#pragma unroll
  for (int o = 16; o; o >>= 1) v = fmaxf(v, __shfl_down_sync(0xffffffffu, v, o));
  return v;
}
__device__ __forceinline__ float sigf(float x) { return 1.f / (1.f + expf(-x)); }

// ---------------- generic tiled fp32 GEMM: C[z] = A[:,k-slice] @ B[k-slice,:] ----------------
// 64x64 tile, K-chunk 16, 256 threads, 4x4 per thread. M,N div by 64; K/gridDim.z div by 16.
__global__ void __launch_bounds__(256) gemm64(
    const float* __restrict__ A, const float* __restrict__ B,
    float* __restrict__ C, const float* __restrict__ bias,
    int M, int N, int K) {
  const int tid   = threadIdx.x;
  const int mBase = blockIdx.y * 64;
  const int nBase = blockIdx.x * 64;
  const int kPer  = K / gridDim.z;
  const int k0    = blockIdx.z * kPer;

  __shared__ float As[16][68];
  __shared__ float Bs[16][68];

  const int tm = (tid >> 4) << 2;
  const int tn = (tid & 15) << 2;
  const int lm = tid >> 2;           // A row within tile
  const int lk = (tid & 3) << 2;     // A k offset (0,4,8,12)
  const int bk = tid >> 4;           // B k row (0..15)
  const int bn = (tid & 15) << 2;    // B n offset

  float acc[4][4] = {};

  for (int kk = 0; kk < kPer; kk += 16) {
    const float4 av = *reinterpret_cast<const float4*>(
        A + (size_t)(mBase + lm) * K + (k0 + kk + lk));
    const float4 bv = *reinterpret_cast<const float4*>(
        B + (size_t)(k0 + kk + bk) * N + (nBase + bn));
    __syncthreads();
    As[lk + 0][lm] = av.x; As[lk + 1][lm] = av.y;
    As[lk + 2][lm] = av.z; As[lk + 3][lm] = av.w;
    Bs[bk][bn + 0] = bv.x; Bs[bk][bn + 1] = bv.y;
    Bs[bk][bn + 2] = bv.z; Bs[bk][bn + 3] = bv.w;
    __syncthreads();
#pragma unroll
    for (int k = 0; k < 16; k++) {
      float a0 = As[k][tm + 0], a1 = As[k][tm + 1], a2 = As[k][tm + 2], a3 = As[k][tm + 3];
      float b0 = Bs[k][tn + 0], b1 = Bs[k][tn + 1], b2 = Bs[k][tn + 2], b3 = Bs[k][tn + 3];
      acc[0][0] = fmaf(a0, b0, acc[0][0]); acc[0][1] = fmaf(a0, b1, acc[0][1]);
      acc[0][2] = fmaf(a0, b2, acc[0][2]); acc[0][3] = fmaf(a0, b3, acc[0][3]);
      acc[1][0] = fmaf(a1, b0, acc[1][0]); acc[1][1] = fmaf(a1, b1, acc[1][1]);
      acc[1][2] = fmaf(a1, b2, acc[1][2]); acc[1][3] = fmaf(a1, b3, acc[1][3]);
      acc[2][0] = fmaf(a2, b0, acc[2][0]); acc[2][1] = fmaf(a2, b1, acc[2][1]);
      acc[2][2] = fmaf(a2, b2, acc[2][2]); acc[2][3] = fmaf(a2, b3, acc[2][3]);
      acc[3][0] = fmaf(a3, b0, acc[3][0]); acc[3][1] = fmaf(a3, b1, acc[3][1]);
      acc[3][2] = fmaf(a3, b2, acc[3][2]); acc[3][3] = fmaf(a3, b3, acc[3][3]);
    }
  }

  float* Cz = C + (size_t)blockIdx.z * M * N;
#pragma unroll
  for (int i = 0; i < 4; i++) {
#pragma unroll
    for (int jj = 0; jj < 4; jj++) {
      const int n = nBase + tn + jj;
      float v = acc[i][jj];
      if (bias) v += bias[n];
      Cz[(size_t)(mBase + tm + i) * N + n] = v;
    }
  }
}

// ---------------- one-time prep kernels ----------------
__global__ void prep_weights(const float* __restrict__ Wd, const float* __restrict__ Wb,
                             const float* __restrict__ Wfc) {
  const int idx = blockIdx.x * 256 + threadIdx.x;
  if (idx < H_ * NHP_) {
    const int k = idx / NHP_, n = idx % NHP_;
    g_Whb[idx] = (n < A_) ? Wd[k * A_ + n] : Wb[k * H_ + (n - A_)];
  }
  if (idx < V_ * H_) {
    const int v = idx / H_, k = idx % H_;
    g_WfcT[idx] = Wfc[k * V_ + v];
  }
}

__global__ void init_kernel(const float* __restrict__ emb) {
  const int b = blockIdx.x, i = threadIdx.x;  // 256
  g_xcat[b * KX_ + i] = emb[68 * E_ + i];     // START_TOK = 68
  if (b == 0 && i == 0) g_done = 0;
}

__global__ void mean_init_kernel(const float* __restrict__ enc,
                                 const float* __restrict__ Wh0, const float* __restrict__ bh0,
                                 const float* __restrict__ Wc0, const float* __restrict__ bc0) {
  const int b = blockIdx.x, e = threadIdx.x;  // 512
  const float* p = enc + (size_t)b * P_ * ENC_ + e;
  float s = 0.f;
#pragma unroll 5
  for (int i = 0; i < P_; i++) s += p[(size_t)i * ENC_];
  __shared__ float ms[ENC_];
  ms[e] = s / 625.f;
  __syncthreads();
  float h = bh0[e], c = bc0[e];
#pragma unroll 4
  for (int k = 0; k < ENC_; k++) {
    const float m = ms[k];
    h = fmaf(m, Wh0[k * H_ + e], h);
    c = fmaf(m, Wc0[k * H_ + e], c);
  }
  g_h[b * H_ + e] = h;
  g_c[b * H_ + e] = c;
  g_xcat[b * KX_ + E_ + H_ + e] = h;
}

// ---------------- finish body (argmax/done/out/emb) — runs as extra block in energy ------------
__device__ __forceinline__ void finish_body(const float* __restrict__ emb,
                                            float* __restrict__ out, int fstep) {
  const int t = threadIdx.x;
  __shared__ float rmax[B_];
  __shared__ int ridx[B_];
  __shared__ int s_done_prev;
  if (t == 0) s_done_prev = g_done;
  if (t < B_) {
    const float* pr = g_preds + t * V_;
    float m = pr[0];
    int mi = 0;
#pragma unroll
    for (int v = 1; v < V_; v++) {
      const float x = pr[v];
      if (x > m) { m = x; mi = v; }
    }
    rmax[t] = m;
    ridx[t] = mi;
  }
  __syncthreads();
  if (t == 0) {
    float bm = rmax[0];
    int bb2 = 0;
    for (int i = 1; i < B_; i++)
      if (rmax[i] > bm) { bm = rmax[i]; bb2 = i; }
    const int flat = bb2 * V_ + ridx[bb2];
    g_done = s_done_prev | (flat == 69);  // END_TOK
  }
  __syncthreads();
  const int dprev = s_done_prev;
  for (int idx = t; idx < B_ * V_; idx += 1024) {
    const int b = idx / V_, v = idx % V_;
    out[(size_t)b * (T_ * V_) + (size_t)fstep * V_ + v] = dprev ? 0.f : g_preds[idx];
  }
  for (int idx = t; idx < B_ * E_; idx += 1024) {
    const int b = idx >> 8, i = idx & 255;
    g_xcat[b * KX_ + i] = emb[ridx[b] * E_ + i];
  }
}

// ---------------- per-step: energies (p-split, 2 blocks per b) + finish of prev step ----------
__global__ void __launch_bounds__(1024) energy_kernel(
    const float* __restrict__ wf, const float* __restrict__ bfp,
    const float* __restrict__ bd, const float* __restrict__ emb,
    float* __restrict__ out, int step) {
  if (blockIdx.x == 2 * B_) {           // finish work for step-1 (independent of energy inputs)
    if (step > 0) finish_body(emb, out, step - 1);
    return;
  }
  const int b  = blockIdx.x >> 1;
  const int ph = blockIdx.x & 1;
  const int p0 = ph ? PSPLIT0 : 0;
  const int p1 = ph ? P_ : PSPLIT0;
  const int t  = threadIdx.x;
  __shared__ float att2_s[A_];
  __shared__ float wf_s[A_];
  __shared__ float s_bf;

  if (t == 0) s_bf = bfp[0];
  if (t < A_) {
    float v = bd[t];
#pragma unroll
    for (int z = 0; z < NZH_; z++) v += g_hproj[z * B_ * NHP_ + b * NHP_ + t];
    att2_s[t] = v;
    wf_s[t] = wf[t];
  }
  __syncthreads();

  const int wid = t >> 5, lane = t & 31;

  // e[p] = sum_a relu(att1 + att2)*wf + bf   (streams fp32 att1: 320KB/block, float4)
  const float* a1b = g_att1 + (size_t)b * (P_ * A_);
  for (int p = p0 + wid; p < p1; p += 32) {
    const float4* ap = reinterpret_cast<const float4*>(a1b + (size_t)p * A_);
    const float4 v0 = ap[lane];
    const float4 v1 = ap[lane + 32];
    float s = 0.f;
    const int a0 = lane * 4;
    const int a1 = 128 + lane * 4;
    s = fmaf(fmaxf(v0.x + att2_s[a0 + 0], 0.f), wf_s[a0 + 0], s);
    s = fmaf(fmaxf(v0.y + att2_s[a0 + 1], 0.f), wf_s[a0 + 1], s);
    s = fmaf(fmaxf(v0.z + att2_s[a0 + 2], 0.f), wf_s[a0 + 2], s);
    s = fmaf(fmaxf(v0.w + att2_s[a0 + 3], 0.f), wf_s[a0 + 3], s);
    s = fmaf(fmaxf(v1.x + att2_s[a1 + 0], 0.f), wf_s[a1 + 0], s);
    s = fmaf(fmaxf(v1.y + att2_s[a1 + 1], 0.f), wf_s[a1 + 1], s);
    s = fmaf(fmaxf(v1.z + att2_s[a1 + 2], 0.f), wf_s[a1 + 2], s);
    s = fmaf(fmaxf(v1.w + att2_s[a1 + 3], 0.f), wf_s[a1 + 3], s);
    s = warp_sum(s);
    if (lane == 0) g_e[b * P_ + p] = s + s_bf;
  }
}

// ---------------- per-step: softmax + gated weighted sum (e-column split, 2 blocks per b) -----
__global__ void __launch_bounds__(512) wsum_kernel(
    const float* __restrict__ enc, const float* __restrict__ bb) {
  const int b  = blockIdx.x >> 1;
  const int eh = blockIdx.x & 1;
  const int t  = threadIdx.x;
  __shared__ float hg_s[256];
  __shared__ float e_s[P_];
  __shared__ float red_s[16];
  __shared__ float part_s[512];
  __shared__ float s_max, s_inv;

  if (t < 256) {
    const int j = eh * 256 + t;
    float x = bb[j];
#pragma unroll
    for (int z = 0; z < NZH_; z++) x += g_hproj[z * B_ * NHP_ + b * NHP_ + A_ + j];
    hg_s[t] = sigf(x);
  }
  // load energies (2.5KB)
  for (int idx = t; idx < P_; idx += 512) e_s[idx] = g_e[b * P_ + idx];
  __syncthreads();

  const int wid = t >> 5, lane = t & 31;

  // softmax over 625
  float lm = e_s[t];
  if (t + 512 < P_) lm = fmaxf(lm, e_s[t + 512]);
  lm = warp_max(lm);
  if (lane == 0) red_s[wid] = lm;
  __syncthreads();
  if (wid == 0) {
    float m = warp_max(lane < 16 ? red_s[lane] : -3.402823466e38f);
    if (lane == 0) s_max = m;
  }
  __syncthreads();
  float ls = 0.f;
  {
    const float ex = expf(e_s[t] - s_max);
    e_s[t] = ex;
    ls = ex;
    if (t + 512 < P_) {
      const float ex2 = expf(e_s[t + 512] - s_max);
      e_s[t + 512] = ex2;
      ls += ex2;
    }
  }
  ls = warp_sum(ls);
  if (lane == 0) red_s[wid] = ls;
  __syncthreads();
  if (wid == 0) {
    float sm = warp_sum(lane < 16 ? red_s[lane] : 0.f);
    if (lane == 0) s_inv = 1.f / sm;
  }
  __syncthreads();

  // weighted sum over this block's 256 e-columns (reads 640KB of enc)
  const int jj  = eh * 256 + (t & 255);
  const int ph2 = t >> 8;   // 0/1: interleaved p
  const float* encb = enc + (size_t)b * (P_ * ENC_) + jj;
  float acc = 0.f;
  int p = ph2;
  for (; p + 14 < P_; p += 16) {
    float v[8];
#pragma unroll
    for (int u = 0; u < 8; u++) v[u] = encb[(size_t)(p + 2 * u) * ENC_];
#pragma unroll
    for (int u = 0; u < 8; u++) acc = fmaf(e_s[p + 2 * u], v[u], acc);
  }
  for (; p < P_; p += 2) acc = fmaf(e_s[p], encb[(size_t)p * ENC_], acc);
  part_s[t] = acc;
  __syncthreads();
  if (t < 256) {
    const float awe = (part_s[t] + part_s[t + 256]) * s_inv;
    g_xcat[b * KX_ + E_ + eh * 256 + t] = hg_s[t] * awe;
  }
}

// ---------------- per-step: LSTM elementwise + preds ----------------
__global__ void __launch_bounds__(512) lstm_kernel(
    const float* __restrict__ bih, const float* __restrict__ bhh,
    const float* __restrict__ bfc) {
  const int b = blockIdx.x, j = threadIdx.x;  // 512
  float gi = bih[j] + bhh[j];
  float gf = bih[j + 512] + bhh[j + 512];
  float gg = bih[j + 1024] + bhh[j + 1024];
  float go = bih[j + 1536] + bhh[j + 1536];
#pragma unroll
  for (int z = 0; z < NZG_; z++) {
    const float* q = g_gates + (size_t)(z * B_ + b) * G4_;
    gi += q[j];
    gf += q[j + 512];
    gg += q[j + 1024];
    go += q[j + 1536];
  }
  const float c  = g_c[b * H_ + j];
  const float cn = sigf(gf) * c + sigf(gi) * tanhf(gg);
  const float hn = sigf(go) * tanhf(cn);
  g_c[b * H_ + j] = cn;
  g_h[b * H_ + j] = hn;
  g_xcat[b * KX_ + E_ + H_ + j] = hn;

  __shared__ float hs[H_];
  hs[j] = hn;
  __syncthreads();
  const int wid = j >> 5, lane = j & 31;
  for (int v = wid; v < V_; v += 16) {
    const float* w = g_WfcT + v * H_;
    float s = 0.f;
#pragma unroll 4
    for (int k = lane; k < H_; k += 32) s = fmaf(hs[k], w[k], s);
    s = warp_sum(s);
    if (lane == 0) g_preds[b * V_ + v] = s + bfc[v];
  }
}

// ---------------- final finish (last step) ----------------
__global__ void __launch_bounds__(1024) finish_kernel(
    const float* __restrict__ emb, float* __restrict__ out, int fstep) {
  finish_body(emb, out, fstep);
}

// ---------------- launch ----------------
extern "C" void kernel_launch(void* const* d_in, const int* in_sizes, int n_in,
                              void* d_out, int out_size) {
  const float* enc = (const float*)d_in[0];
  const float* emb = (const float*)d_in[1];
  const float* We  = (const float*)d_in[2];
  const float* be  = (const float*)d_in[3];
  const float* Wd  = (const float*)d_in[4];
  const float* bd  = (const float*)d_in[5];
  const float* wf  = (const float*)d_in[6];
  const float* bf  = (const float*)d_in[7];
  const float* Wh0 = (const float*)d_in[8];
  const float* bh0 = (const float*)d_in[9];
  const float* Wc0 = (const float*)d_in[10];
  const float* bc0 = (const float*)d_in[11];
  const float* Wb  = (const float*)d_in[12];
  const float* bb  = (const float*)d_in[13];
  const float* Wih = (const float*)d_in[14];
  const float* Whh = (const float*)d_in[15];
  const float* bih = (const float*)d_in[16];
  const float* bhh = (const float*)d_in[17];
  const float* Wfc = (const float*)d_in[18];
  const float* bfc = (const float*)d_in[19];
  float* out = (float*)d_out;

  float *p_att1, *p_h, *p_xcat, *p_hproj, *p_gates, *p_Wcat, *p_Whb;
  cudaGetSymbolAddress((void**)&p_att1,  g_att1);
  cudaGetSymbolAddress((void**)&p_h,     g_h);
  cudaGetSymbolAddress((void**)&p_xcat,  g_xcat);
  cudaGetSymbolAddress((void**)&p_hproj, g_hproj);
  cudaGetSymbolAddress((void**)&p_gates, g_gates);
  cudaGetSymbolAddress((void**)&p_Wcat,  g_Wcat);
  cudaGetSymbolAddress((void**)&p_Whb,   g_Whb);

  // concat [Wih ; Whh] -> Wcat (async D2D copies; capture-legal)
  cudaMemcpyAsync(p_Wcat, Wih, sizeof(float) * (size_t)768 * G4_,
                  cudaMemcpyDeviceToDevice, 0);
  cudaMemcpyAsync(p_Wcat + (size_t)768 * G4_, Whh, sizeof(float) * (size_t)512 * G4_,
                  cudaMemcpyDeviceToDevice, 0);

  prep_weights<<<1536, 256>>>(Wd, Wb, Wfc);
  init_kernel<<<B_, 256>>>(emb);
  mean_init_kernel<<<B_, 512>>>(enc, Wh0, bh0, Wc0, bc0);

  // att1 = enc @ We + be : M=80000, N=256, K=512 (fp32)
  gemm64<<<dim3(256 / 64, (B_ * P_) / 64, 1), 256>>>(enc, We, p_att1, be,
                                                     B_ * P_, 256, 512);

  for (int step = 0; step < T_; step++) {
    // hproj = h @ [Wd|Wb]  : M=128, N=768, K=512, Ksplit=8
    gemm64<<<dim3(NHP_ / 64, B_ / 64, NZH_), 256>>>(p_h, p_Whb, p_hproj, nullptr,
                                                    B_, NHP_, 512);
    // energies (+ finish of step-1 in block 256)
    energy_kernel<<<2 * B_ + 1, 1024>>>(wf, bf, bd, emb, out, step);
    // softmax + gated weighted sum
    wsum_kernel<<<2 * B_, 512>>>(enc, bb);
    // gates = xcat @ Wcat : M=128, N=2048, K=1280, Ksplit=8
    gemm64<<<dim3(G4_ / 64, B_ / 64, NZG_), 256>>>(p_xcat, p_Wcat, p_gates, nullptr,
                                                   B_, G4_, KX_);
    lstm_kernel<<<B_, 512>>>(bih, bhh, bfc);
  }
  finish_kernel<<<1, 1024>>>(emb, out, T_ - 1);
}

// round 12
// speedup vs baseline: 1.4858x; 1.0017x over previous
#include <cuda_runtime.h>
#include <cstdint>
#include <cstddef>

#define B_   128
#define P_   625
#define ENC_ 512
#define A_   256
#define E_   256
#define H_   512
#define V_   70
#define T_   70
#define G4_  2048   // 4*H
#define KX_  1280   // E + ENC + H
#define NHP_ 768    // A + H  (att2 | gate-pre)
#define NZH_ 8      // K-split for hproj / gates_p1 / gates_p2
#define NZT_ 16     // total gates partial slots (8 p1 + 8 p2)
#define PSPLIT0 313 // energy p-range split

// ---------------- device scratch (static; no runtime allocation) ----------------
__device__ float g_att1[(size_t)B_ * P_ * A_];   // 81.92 MB (fp32 — precision is load-bearing)
__device__ float g_e[B_ * P_];                   // raw energies per step
__device__ float g_h[B_ * H_];
__device__ float g_c[B_ * H_];
__device__ float g_xcat[B_ * KX_];               // [emb(256) | awe_gated(512) | (unused h)]
__device__ float g_hproj[NZH_ * B_ * NHP_];      // K-split partials of h @ [Wd|Wb]
__device__ float g_gates[NZT_ * B_ * G4_];       // partials: z 0..7 = h@Whh, z 8..15 = [emb|awe]@Wih
__device__ float g_preds[B_ * V_];
__device__ float g_Wcat[(size_t)KX_ * G4_];      // [Wih ; Whh]  10.49 MB
__device__ float g_Whb[H_ * NHP_];               // columns [Wd | Wb]
__device__ float g_WfcT[V_ * H_];                // Wfc transposed
__device__ int   g_done;

// ---------------- helpers ----------------
__device__ __forceinline__ float warp_sum(float v) {
#pragma unroll
  for (int o = 16; o; o >>= 1) v += __shfl_down_sync(0xffffffffu, v, o);
  return v;
}
__device__ __forceinline__ float warp_max(float v) {
#pragma unroll
  for (int o = 16; o; o >>= 1) v = fmaxf(v, __shfl_down_sync(0xffffffffu, v, o));
  return v;
}
__device__ __forceinline__ float sigf(float x) { return 1.f / (1.f + expf(-x)); }

// ---------------- shared GEMM tile body: C = A[:,k0:k0+kPer] @ B[k0:k0+kPer,:] -------------
// 64x64 tile, K-chunk 16, 256 threads, 4x4 per thread. kPer divisible by 16.
__device__ __forceinline__ void gemm_body(
    const float* __restrict__ A, int lda,
    const float* __restrict__ Bm, int N,
    float* __restrict__ C, const float* __restrict__ bias,
    int kPer, int k0, int mBase, int nBase) {
  const int tid = threadIdx.x;

  __shared__ float As[16][68];
  __shared__ float Bs[16][68];

  const int tm = (tid >> 4) << 2;
  const int tn = (tid & 15) << 2;
  const int lm = tid >> 2;           // A row within tile
  const int lk = (tid & 3) << 2;     // A k offset (0,4,8,12)
  const int bk = tid >> 4;           // B k row (0..15)
  const int bn = (tid & 15) << 2;    // B n offset

  float acc[4][4] = {};

  for (int kk = 0; kk < kPer; kk += 16) {
    const float4 av = *reinterpret_cast<const float4*>(
        A + (size_t)(mBase + lm) * lda + (k0 + kk + lk));
    const float4 bv = *reinterpret_cast<const float4*>(
        Bm + (size_t)(k0 + kk + bk) * N + (nBase + bn));
    __syncthreads();
    As[lk + 0][lm] = av.x; As[lk + 1][lm] = av.y;
    As[lk + 2][lm] = av.z; As[lk + 3][lm] = av.w;
    Bs[bk][bn + 0] = bv.x; Bs[bk][bn + 1] = bv.y;
    Bs[bk][bn + 2] = bv.z; Bs[bk][bn + 3] = bv.w;
    __syncthreads();
#pragma unroll
    for (int k = 0; k < 16; k++) {
      float a0 = As[k][tm + 0], a1 = As[k][tm + 1], a2 = As[k][tm + 2], a3 = As[k][tm + 3];
      float b0 = Bs[k][tn + 0], b1 = Bs[k][tn + 1], b2 = Bs[k][tn + 2], b3 = Bs[k][tn + 3];
      acc[0][0] = fmaf(a0, b0, acc[0][0]); acc[0][1] = fmaf(a0, b1, acc[0][1]);
      acc[0][2] = fmaf(a0, b2, acc[0][2]); acc[0][3] = fmaf(a0, b3, acc[0][3]);
      acc[1][0] = fmaf(a1, b0, acc[1][0]); acc[1][1] = fmaf(a1, b1, acc[1][1]);
      acc[1][2] = fmaf(a1, b2, acc[1][2]); acc[1][3] = fmaf(a1, b3, acc[1][3]);
      acc[2][0] = fmaf(a2, b0, acc[2][0]); acc[2][1] = fmaf(a2, b1, acc[2][1]);
      acc[2][2] = fmaf(a2, b2, acc[2][2]); acc[2][3] = fmaf(a2, b3, acc[2][3]);
      acc[3][0] = fmaf(a3, b0, acc[3][0]); acc[3][1] = fmaf(a3, b1, acc[3][1]);
      acc[3][2] = fmaf(a3, b2, acc[3][2]); acc[3][3] = fmaf(a3, b3, acc[3][3]);
    }
  }

#pragma unroll
  for (int i = 0; i < 4; i++) {
#pragma unroll
    for (int jj = 0; jj < 4; jj++) {
      const int n = nBase + tn + jj;
      float v = acc[i][jj];
      if (bias) v += bias[n];
      C[(size_t)(mBase + tm + i) * N + n] = v;
    }
  }
}

// ---------------- generic GEMM (z-split partials): C[z] = A[:,kslice] @ B[kslice,:] ----------
__global__ void __launch_bounds__(256) gemm64(
    const float* __restrict__ A, int lda, const float* __restrict__ B,
    float* __restrict__ C, const float* __restrict__ bias,
    int M, int N, int K) {
  const int kPer = K / gridDim.z;
  gemm_body(A, lda, B, N, C + (size_t)blockIdx.z * M * N, bias,
            kPer, blockIdx.z * kPer, blockIdx.y * 64, blockIdx.x * 64);
}

// ---------------- per-step launch 1: hproj (blocks 0..11) + gates_p1 = h@Whh (12..43) --------
__global__ void __launch_bounds__(256) dual_gemm(void) {
  const int bx = blockIdx.x;
  const int z  = blockIdx.z;
  const int k0 = z * 64;                 // K=512, split 8
  const float* Bm;
  float* C;
  int N, nBase;
  if (bx < 12) {                          // hproj = h @ [Wd|Wb]
    Bm = g_Whb; N = NHP_;
    C = g_hproj + (size_t)z * B_ * NHP_;
    nBase = bx * 64;
  } else {                                // gates_p1 = h @ Wcat[768:1280,:]
    Bm = g_Wcat + (size_t)768 * G4_; N = G4_;
    C = g_gates + (size_t)z * B_ * G4_;
    nBase = (bx - 12) * 64;
  }
  gemm_body(g_h, H_, Bm, N, C, nullptr, 64, k0, blockIdx.y * 64, nBase);
}

// ---------------- one-time prep kernels ----------------
__global__ void prep_weights(const float* __restrict__ Wd, const float* __restrict__ Wb,
                             const float* __restrict__ Wfc) {
  const int idx = blockIdx.x * 256 + threadIdx.x;
  if (idx < H_ * NHP_) {
    const int k = idx / NHP_, n = idx % NHP_;
    g_Whb[idx] = (n < A_) ? Wd[k * A_ + n] : Wb[k * H_ + (n - A_)];
  }
  if (idx < V_ * H_) {
    const int v = idx / H_, k = idx % H_;
    g_WfcT[idx] = Wfc[k * V_ + v];
  }
}

__global__ void init_kernel(const float* __restrict__ emb) {
  const int b = blockIdx.x, i = threadIdx.x;  // 256
  g_xcat[b * KX_ + i] = emb[68 * E_ + i];     // START_TOK = 68
  if (b == 0 && i == 0) g_done = 0;
}

__global__ void mean_init_kernel(const float* __restrict__ enc,
                                 const float* __restrict__ Wh0, const float* __restrict__ bh0,
                                 const float* __restrict__ Wc0, const float* __restrict__ bc0) {
  const int b = blockIdx.x, e = threadIdx.x;  // 512
  const float* p = enc + (size_t)b * P_ * ENC_ + e;
  float s = 0.f;
#pragma unroll 5
  for (int i = 0; i < P_; i++) s += p[(size_t)i * ENC_];
  __shared__ float ms[ENC_];
  ms[e] = s / 625.f;
  __syncthreads();
  float h = bh0[e], c = bc0[e];
#pragma unroll 4
  for (int k = 0; k < ENC_; k++) {
    const float m = ms[k];
    h = fmaf(m, Wh0[k * H_ + e], h);
    c = fmaf(m, Wc0[k * H_ + e], c);
  }
  g_h[b * H_ + e] = h;
  g_c[b * H_ + e] = c;
}

// ---------------- finish body (argmax/done/out/emb) — runs as extra block in energy ------------
__device__ __forceinline__ void finish_body(const float* __restrict__ emb,
                                            float* __restrict__ out, int fstep) {
  const int t = threadIdx.x;
  __shared__ float rmax[B_];
  __shared__ int ridx[B_];
  __shared__ int s_done_prev;
  if (t == 0) s_done_prev = g_done;
  if (t < B_) {
    const float* pr = g_preds + t * V_;
    float m = pr[0];
    int mi = 0;
#pragma unroll
    for (int v = 1; v < V_; v++) {
      const float x = pr[v];
      if (x > m) { m = x; mi = v; }
    }
    rmax[t] = m;
    ridx[t] = mi;
  }
  __syncthreads();
  if (t == 0) {
    float bm = rmax[0];
    int bb2 = 0;
    for (int i = 1; i < B_; i++)
      if (rmax[i] > bm) { bm = rmax[i]; bb2 = i; }
    const int flat = bb2 * V_ + ridx[bb2];
    g_done = s_done_prev | (flat == 69);  // END_TOK
  }
  __syncthreads();
  const int dprev = s_done_prev;
  for (int idx = t; idx < B_ * V_; idx += 1024) {
    const int b = idx / V_, v = idx % V_;
    out[(size_t)b * (T_ * V_) + (size_t)fstep * V_ + v] = dprev ? 0.f : g_preds[idx];
  }
  for (int idx = t; idx < B_ * E_; idx += 1024) {
    const int b = idx >> 8, i = idx & 255;
    g_xcat[b * KX_ + i] = emb[ridx[b] * E_ + i];
  }
}

// ---------------- per-step: energies (p-split, 2 blocks per b) + finish of prev step ----------
__global__ void __launch_bounds__(1024) energy_kernel(
    const float* __restrict__ wf, const float* __restrict__ bfp,
    const float* __restrict__ bd, const float* __restrict__ emb,
    float* __restrict__ out, int step) {
  if (blockIdx.x == 2 * B_) {           // finish work for step-1 (independent of energy inputs)
    if (step > 0) finish_body(emb, out, step - 1);
    return;
  }
  const int b  = blockIdx.x >> 1;
  const int ph = blockIdx.x & 1;
  const int p0 = ph ? PSPLIT0 : 0;
  const int p1 = ph ? P_ : PSPLIT0;
  const int t  = threadIdx.x;
  __shared__ float att2_s[A_];
  __shared__ float wf_s[A_];
  __shared__ float s_bf;

  if (t == 0) s_bf = bfp[0];
  if (t < A_) {
    float v = bd[t];
#pragma unroll
    for (int z = 0; z < NZH_; z++) v += g_hproj[z * B_ * NHP_ + b * NHP_ + t];
    att2_s[t] = v;
    wf_s[t] = wf[t];
  }
  __syncthreads();

  const int wid = t >> 5, lane = t & 31;

  // e[p] = sum_a relu(att1 + att2)*wf + bf   (streams fp32 att1: 320KB/block, float4)
  const float* a1b = g_att1 + (size_t)b * (P_ * A_);
  for (int p = p0 + wid; p < p1; p += 32) {
    const float4* ap = reinterpret_cast<const float4*>(a1b + (size_t)p * A_);
    const float4 v0 = ap[lane];
    const float4 v1 = ap[lane + 32];
    float s = 0.f;
    const int a0 = lane * 4;
    const int a1 = 128 + lane * 4;
    s = fmaf(fmaxf(v0.x + att2_s[a0 + 0], 0.f), wf_s[a0 + 0], s);
    s = fmaf(fmaxf(v0.y + att2_s[a0 + 1], 0.f), wf_s[a0 + 1], s);
    s = fmaf(fmaxf(v0.z + att2_s[a0 + 2], 0.f), wf_s[a0 + 2], s);
    s = fmaf(fmaxf(v0.w + att2_s[a0 + 3], 0.f), wf_s[a0 + 3], s);
    s = fmaf(fmaxf(v1.x + att2_s[a1 + 0], 0.f), wf_s[a1 + 0], s);
    s = fmaf(fmaxf(v1.y + att2_s[a1 + 1], 0.f), wf_s[a1 + 1], s);
    s = fmaf(fmaxf(v1.z + att2_s[a1 + 2], 0.f), wf_s[a1 + 2], s);
    s = fmaf(fmaxf(v1.w + att2_s[a1 + 3], 0.f), wf_s[a1 + 3], s);
    s = warp_sum(s);
    if (lane == 0) g_e[b * P_ + p] = s + s_bf;
  }
}

// ---------------- per-step: softmax + gated weighted sum (4 column-slices per b) --------------
__global__ void __launch_bounds__(512) wsum_kernel(
    const float* __restrict__ enc, const float* __restrict__ bb) {
  const int b = blockIdx.x >> 2;
  const int q = blockIdx.x & 3;          // 128-column slice
  const int t = threadIdx.x;
  __shared__ float hg_s[128];
  __shared__ float e_s[P_];
  __shared__ float red_s[16];
  __shared__ float part_s[512];
  __shared__ float s_max, s_inv;

  if (t < 128) {
    const int j = q * 128 + t;
    float x = bb[j];
#pragma unroll
    for (int z = 0; z < NZH_; z++) x += g_hproj[z * B_ * NHP_ + b * NHP_ + A_ + j];
    hg_s[t] = sigf(x);
  }
  // load energies (2.5KB)
  for (int idx = t; idx < P_; idx += 512) e_s[idx] = g_e[b * P_ + idx];
  __syncthreads();

  const int wid = t >> 5, lane = t & 31;

  // softmax over 625
  float lm = e_s[t];
  if (t + 512 < P_) lm = fmaxf(lm, e_s[t + 512]);
  lm = warp_max(lm);
  if (lane == 0) red_s[wid] = lm;
  __syncthreads();
  if (wid == 0) {
    float m = warp_max(lane < 16 ? red_s[lane] : -3.402823466e38f);
    if (lane == 0) s_max = m;
  }
  __syncthreads();
  float ls = 0.f;
  {
    const float ex = expf(e_s[t] - s_max);
    e_s[t] = ex;
    ls = ex;
    if (t + 512 < P_) {
      const float ex2 = expf(e_s[t + 512] - s_max);
      e_s[t + 512] = ex2;
      ls += ex2;
    }
  }
  ls = warp_sum(ls);
  if (lane == 0) red_s[wid] = ls;
  __syncthreads();
  if (wid == 0) {
    float sm = warp_sum(lane < 16 ? red_s[lane] : 0.f);
    if (lane == 0) s_inv = 1.f / sm;
  }
  __syncthreads();

  // weighted sum over this block's 128 e-columns (reads 320KB of enc), 4 interleaved p-phases
  const int jj = q * 128 + (t & 127);
  const int ph = t >> 7;   // 0..3
  const float* encb = enc + (size_t)b * (P_ * ENC_) + jj;
  float acc = 0.f;
  int p = ph;
  for (; p + 12 < P_; p += 16) {
    float v[4];
#pragma unroll
    for (int u = 0; u < 4; u++) v[u] = encb[(size_t)(p + 4 * u) * ENC_];
#pragma unroll
    for (int u = 0; u < 4; u++) acc = fmaf(e_s[p + 4 * u], v[u], acc);
  }
  for (; p < P_; p += 4) acc = fmaf(e_s[p], encb[(size_t)p * ENC_], acc);
  part_s[t] = acc;
  __syncthreads();
  if (t < 128) {
    const float awe =
        (part_s[t] + part_s[t + 128] + part_s[t + 256] + part_s[t + 384]) * s_inv;
    g_xcat[b * KX_ + E_ + q * 128 + t] = hg_s[t] * awe;
  }
}

// ---------------- per-step: LSTM elementwise + preds ----------------
__global__ void __launch_bounds__(512) lstm_kernel(
    const float* __restrict__ bih, const float* __restrict__ bhh,
    const float* __restrict__ bfc) {
  const int b = blockIdx.x, j = threadIdx.x;  // 512
  float gi = bih[j] + bhh[j];
  float gf = bih[j + 512] + bhh[j + 512];
  float gg = bih[j + 1024] + bhh[j + 1024];
  float go = bih[j + 1536] + bhh[j + 1536];
#pragma unroll
  for (int z = 0; z < NZT_; z++) {
    const float* q = g_gates + (size_t)(z * B_ + b) * G4_;
    gi += q[j];
    gf += q[j + 512];
    gg += q[j + 1024];
    go += q[j + 1536];
  }
  const float c  = g_c[b * H_ + j];
  const float cn = sigf(gf) * c + sigf(gi) * tanhf(gg);
  const float hn = sigf(go) * tanhf(cn);
  g_c[b * H_ + j] = cn;
  g_h[b * H_ + j] = hn;

  __shared__ float hs[H_];
  hs[j] = hn;
  __syncthreads();
  const int wid = j >> 5, lane = j & 31;
  for (int v = wid; v < V_; v += 16) {
    const float* w = g_WfcT + v * H_;
    float s = 0.f;
#pragma unroll 4
    for (int k = lane; k < H_; k += 32) s = fmaf(hs[k], w[k], s);
    s = warp_sum(s);
    if (lane == 0) g_preds[b * V_ + v] = s + bfc[v];
  }
}

// ---------------- final finish (last step) ----------------
__global__ void __launch_bounds__(1024) finish_kernel(
    const float* __restrict__ emb, float* __restrict__ out, int fstep) {
  finish_body(emb, out, fstep);
}

// ---------------- launch ----------------
extern "C" void kernel_launch(void* const* d_in, const int* in_sizes, int n_in,
                              void* d_out, int out_size) {
  const float* enc = (const float*)d_in[0];
  const float* emb = (const float*)d_in[1];
  const float* We  = (const float*)d_in[2];
  const float* be  = (const float*)d_in[3];
  const float* Wd  = (const float*)d_in[4];
  const float* bd  = (const float*)d_in[5];
  const float* wf  = (const float*)d_in[6];
  const float* bf  = (const float*)d_in[7];
  const float* Wh0 = (const float*)d_in[8];
  const float* bh0 = (const float*)d_in[9];
  const float* Wc0 = (const float*)d_in[10];
  const float* bc0 = (const float*)d_in[11];
  const float* Wb  = (const float*)d_in[12];
  const float* bb  = (const float*)d_in[13];
  const float* Wih = (const float*)d_in[14];
  const float* Whh = (const float*)d_in[15];
  const float* bih = (const float*)d_in[16];
  const float* bhh = (const float*)d_in[17];
  const float* Wfc = (const float*)d_in[18];
  const float* bfc = (const float*)d_in[19];
  float* out = (float*)d_out;

  float *p_att1, *p_xcat, *p_gates, *p_Wcat;
  cudaGetSymbolAddress((void**)&p_att1,  g_att1);
  cudaGetSymbolAddress((void**)&p_xcat,  g_xcat);
  cudaGetSymbolAddress((void**)&p_gates, g_gates);
  cudaGetSymbolAddress((void**)&p_Wcat,  g_Wcat);

  // concat [Wih ; Whh] -> Wcat (async D2D copies; capture-legal)
  cudaMemcpyAsync(p_Wcat, Wih, sizeof(float) * (size_t)768 * G4_,
                  cudaMemcpyDeviceToDevice, 0);
  cudaMemcpyAsync(p_Wcat + (size_t)768 * G4_, Whh, sizeof(float) * (size_t)512 * G4_,
                  cudaMemcpyDeviceToDevice, 0);

  prep_weights<<<1536, 256>>>(Wd, Wb, Wfc);
  init_kernel<<<B_, 256>>>(emb);
  mean_init_kernel<<<B_, 512>>>(enc, Wh0, bh0, Wc0, bc0);

  // att1 = enc @ We + be : M=80000, N=256, K=512 (fp32)
  gemm64<<<dim3(256 / 64, (B_ * P_) / 64, 1), 256>>>(enc, 512, We, p_att1, be,
                                                     B_ * P_, 256, 512);

  for (int step = 0; step < T_; step++) {
    // hproj (12 xblocks) + gates_p1 = h@Whh (32 xblocks); K=512, Ksplit=8
    dual_gemm<<<dim3(44, B_ / 64, NZH_), 256>>>();
    // energies (+ finish of step-1 in block 256)
    energy_kernel<<<2 * B_ + 1, 1024>>>(wf, bf, bd, emb, out, step);
    // softmax + gated weighted sum (4 slices per b)
    wsum_kernel<<<4 * B_, 512>>>(enc, bb);
    // gates_p2 = xcat[:,0:768] @ Wcat[0:768,:] : Ksplit=8 -> partial slots 8..15
    gemm64<<<dim3(G4_ / 64, B_ / 64, NZH_), 256>>>(
        p_xcat, KX_, p_Wcat, p_gates + (size_t)NZH_ * B_ * G4_, nullptr,
        B_, G4_, 768);
    lstm_kernel<<<B_, 512>>>(bih, bhh, bfc);
  }
  finish_kernel<<<1, 1024>>>(emb, out, T_ - 1);
}